// round 17
// baseline (speedup 1.0000x reference)
#include <cuda_runtime.h>
#include <cuda_bf16.h>
#include <math.h>
#include <stdint.h>

#define BB 4
#define TT 1024
#define CC 768
#define HH 12
#define DHH 64
#define LL 6
#define VV 32000
#define MM (BB*TT)       // 4096
#define FF (4*CC)        // 3072

// ---------------- scratch (device globals; no allocation in kernel_launch) ----
__device__ float g_x[MM*CC];
__device__ float g_h[MM*CC];
__device__ float g_q[MM*CC];
__device__ float g_k[MM*CC];
__device__ float g_v[MM*CC];
__device__ float g_y[MM*CC];
__device__ float g_ff[MM*FF];
__device__ __nv_bfloat16 g_ab[MM*CC];          // bf16 final hidden (head A operand)
__device__ __nv_bfloat16 g_whb[(size_t)VV*CC]; // bf16 Whead, TRANSPOSED to [n][k]

// ---------------- embedding: x = tok_emb[idx] + pos_emb ----------------------
__global__ void embed_kernel(const int* __restrict__ idx, const float* __restrict__ tok,
                             const float* __restrict__ pos) {
    int i = blockIdx.x * 256 + threadIdx.x;
    if (i >= MM * CC) return;
    int row = i / CC, c = i - row * CC;
    int t = row & (TT - 1);
    g_x[i] = tok[(size_t)idx[row] * CC + c] + pos[t * CC + c];
}

// ---------------- layernorm: one WARP per row, shfl-only reductions ----------
template <int WRITE_BF16>
__global__ __launch_bounds__(256) void ln_kernel(const float* __restrict__ in,
                                                 const float* __restrict__ gamma,
                                                 const float* __restrict__ beta,
                                                 float* __restrict__ out) {
    const int w = threadIdx.x >> 5, lane = threadIdx.x & 31;
    const int row = blockIdx.x * 8 + w;
    const float* x = in + (size_t)row * CC;
    float4 v[6];
    float s = 0.f;
    #pragma unroll
    for (int j = 0; j < 6; j++) {
        v[j] = *(const float4*)&x[(j * 32 + lane) * 4];
        s += (v[j].x + v[j].y) + (v[j].z + v[j].w);
    }
    #pragma unroll
    for (int o = 16; o > 0; o >>= 1) s += __shfl_xor_sync(0xffffffffu, s, o);
    float mean = s * (1.0f / CC);
    float sq = 0.f;
    #pragma unroll
    for (int j = 0; j < 6; j++) {
        float a = v[j].x - mean, b = v[j].y - mean, c = v[j].z - mean, d = v[j].w - mean;
        sq += (a * a + b * b) + (c * c + d * d);
    }
    #pragma unroll
    for (int o = 16; o > 0; o >>= 1) sq += __shfl_xor_sync(0xffffffffu, sq, o);
    float r = rsqrtf(sq * (1.0f / CC) + 1e-5f);
    float* o = out + (size_t)row * CC;
    #pragma unroll
    for (int j = 0; j < 6; j++) {
        int c0 = (j * 32 + lane) * 4;
        float4 g4 = *(const float4*)&gamma[c0];
        float4 b4 = *(const float4*)&beta[c0];
        float4 ov;
        ov.x = (v[j].x - mean) * r * g4.x + b4.x;
        ov.y = (v[j].y - mean) * r * g4.y + b4.y;
        ov.z = (v[j].z - mean) * r * g4.z + b4.z;
        ov.w = (v[j].w - mean) * r * g4.w + b4.w;
        *(float4*)&o[c0] = ov;
        if (WRITE_BF16) {
            __nv_bfloat162 lo = __floats2bfloat162_rn(ov.x, ov.y);
            __nv_bfloat162 hi = __floats2bfloat162_rn(ov.z, ov.w);
            *(__nv_bfloat162*)&g_ab[(size_t)row * CC + c0]     = lo;
            *(__nv_bfloat162*)&g_ab[(size_t)row * CC + c0 + 2] = hi;
        }
    }
}

// ---------------- fused split-K reduce + residual + bias + LayerNorm ---------
template <int WRITE_BF16>
__global__ __launch_bounds__(256) void reduce3_ln_kernel(const float* __restrict__ p0,
                                                         const float* __restrict__ p1,
                                                         const float* __restrict__ p2,
                                                         const float* __restrict__ bias,
                                                         float* __restrict__ xres,
                                                         const float* __restrict__ gamma,
                                                         const float* __restrict__ beta,
                                                         float* __restrict__ hout) {
    const int w = threadIdx.x >> 5, lane = threadIdx.x & 31;
    const int row = blockIdx.x * 8 + w;
    const size_t base = (size_t)row * CC;
    float4 v[6];
    float s = 0.f;
    #pragma unroll
    for (int j = 0; j < 6; j++) {
        int c0 = (j * 32 + lane) * 4;
        float4 a = *(const float4*)&p0[base + c0];
        float4 b = *(const float4*)&p1[base + c0];
        float4 c = *(const float4*)&p2[base + c0];
        float4 r = *(const float4*)&xres[base + c0];
        float4 bb = *(const float4*)&bias[c0];
        float4 o;
        o.x = r.x + bb.x + (a.x + b.x) + c.x;
        o.y = r.y + bb.y + (a.y + b.y) + c.y;
        o.z = r.z + bb.z + (a.z + b.z) + c.z;
        o.w = r.w + bb.w + (a.w + b.w) + c.w;
        *(float4*)&xres[base + c0] = o;
        v[j] = o;
        s += (o.x + o.y) + (o.z + o.w);
    }
    #pragma unroll
    for (int o = 16; o > 0; o >>= 1) s += __shfl_xor_sync(0xffffffffu, s, o);
    float mean = s * (1.0f / CC);
    float sq = 0.f;
    #pragma unroll
    for (int j = 0; j < 6; j++) {
        float a = v[j].x - mean, b = v[j].y - mean, c = v[j].z - mean, d = v[j].w - mean;
        sq += (a * a + b * b) + (c * c + d * d);
    }
    #pragma unroll
    for (int o = 16; o > 0; o >>= 1) sq += __shfl_xor_sync(0xffffffffu, sq, o);
    float r = rsqrtf(sq * (1.0f / CC) + 1e-5f);
    #pragma unroll
    for (int j = 0; j < 6; j++) {
        int c0 = (j * 32 + lane) * 4;
        float4 g4 = *(const float4*)&gamma[c0];
        float4 b4 = *(const float4*)&beta[c0];
        float4 ov;
        ov.x = (v[j].x - mean) * r * g4.x + b4.x;
        ov.y = (v[j].y - mean) * r * g4.y + b4.y;
        ov.z = (v[j].z - mean) * r * g4.z + b4.z;
        ov.w = (v[j].w - mean) * r * g4.w + b4.w;
        *(float4*)&hout[base + c0] = ov;
        if (WRITE_BF16) {
            __nv_bfloat162 lo = __floats2bfloat162_rn(ov.x, ov.y);
            __nv_bfloat162 hi = __floats2bfloat162_rn(ov.z, ov.w);
            *(__nv_bfloat162*)&g_ab[base + c0]     = lo;
            *(__nv_bfloat162*)&g_ab[base + c0 + 2] = hi;
        }
    }
}

// ---------------- shared helpers ---------------------------------------------
__device__ __forceinline__ void cp16(void* dst, const void* src) {
    uint32_t d = (uint32_t)__cvta_generic_to_shared(dst);
    asm volatile("cp.async.cg.shared.global [%0], [%1], 16;" :: "r"(d), "l"(src) : "memory");
}

__device__ __forceinline__ float gelu_f(float v) {
    return 0.5f * v * (1.0f + erff(v * 0.7071067811865475f));
}

// ---------------- SGEMM v4: 128x128x32, cp.async B, LDG/STS A ----------------
// One barrier per 32-deep k-tile; B streams straight to smem (no staging regs).
#define SGEMM_SMEM_BYTES ((2 * 32 * 132 + 2 * 32 * 128) * 4)   // 66,560 B

template <int MODE>
__device__ __forceinline__ void sgemm_body(const float* __restrict__ A,
                                           const float* __restrict__ B,
                                           const float* __restrict__ bias,
                                           const float* __restrict__ Res,
                                           float* __restrict__ Cout,
                                           int N, int K, int lda,
                                           int rowBase, int colBase) {
    extern __shared__ __align__(16) float smp[];
    float* As = smp;                     // [2][32][132]
    float* Bs = smp + 2 * 32 * 132;      // [2][32][128]
    #define AS_(b,k,i) As[((b) * 32 + (k)) * 132 + (i)]
    #define BS_(b,k,i) Bs[((b) * 32 + (k)) * 128 + (i)]

    const int tid = threadIdx.x;
    const int warp = tid >> 5, lane = tid & 31;
    const int warp_m = warp & 1;
    const int warp_n = warp >> 1;
    const int lane_m = lane & 7;
    const int lane_n = lane >> 3;
    const int tm0 = warp_m * 64 + lane_m * 4;
    const int tn0 = warp_n * 32 + lane_n * 4;

    // A: row = tid>>1, cols (tid&1)*4 + {0,8,16,24} (+e) -> conflict-free STS
    const int aRow = tid >> 1, aCol = (tid & 1) * 4;
    // B: row = tid>>3, colbase = (tid&7)*16, 4 x 16B cp.async chunks
    const int bRow = tid >> 3, bCol = (tid & 7) * 16;
    const float* Aptr = A + (size_t)(rowBase + aRow) * lda + aCol;
    const float* Bptr = B + (size_t)bRow * N + colBase + bCol;

    float acc[8][8];
    #pragma unroll
    for (int i = 0; i < 8; i++)
        #pragma unroll
        for (int j = 0; j < 8; j++) acc[i][j] = 0.f;

    // ---- prologue: tile 0 ----
    {
        const float* bs = Bptr;
        #pragma unroll
        for (int j = 0; j < 4; j++) cp16(&BS_(0, bRow, bCol + j * 4), bs + j * 4);
        asm volatile("cp.async.commit_group;" ::: "memory");
        float4 ar[4];
        #pragma unroll
        for (int j = 0; j < 4; j++) ar[j] = *(const float4*)(Aptr + j * 8);
        #pragma unroll
        for (int j = 0; j < 4; j++) {
            AS_(0, aCol + j * 8 + 0, aRow) = ar[j].x;
            AS_(0, aCol + j * 8 + 1, aRow) = ar[j].y;
            AS_(0, aCol + j * 8 + 2, aRow) = ar[j].z;
            AS_(0, aCol + j * 8 + 3, aRow) = ar[j].w;
        }
    }

    const int nt = K >> 5;
    for (int t = 1; t < nt; ++t) {
        const int cur = (t - 1) & 1, nxt = t & 1;
        // prefetch A(t) into regs (latency hidden behind compute)
        float4 ar[4];
        #pragma unroll
        for (int j = 0; j < 4; j++) ar[j] = *(const float4*)(Aptr + t * 32 + j * 8);
        // wait for B(cur); barrier makes A(cur) stores + B arrival visible
        asm volatile("cp.async.wait_group 0;" ::: "memory");
        __syncthreads();
        // stream B(t) into nxt (overlaps compute below)
        {
            const float* bs = Bptr + (size_t)t * 32 * N;
            #pragma unroll
            for (int j = 0; j < 4; j++) cp16(&BS_(nxt, bRow, bCol + j * 4), bs + j * 4);
            asm volatile("cp.async.commit_group;" ::: "memory");
        }
        // compute 32-deep on cur
        for (int kh = 0; kh < 2; kh++) {
            #pragma unroll
            for (int kq = 0; kq < 16; kq++) {
                const int kk = kh * 16 + kq;
                float4 fa0 = *(const float4*)(&AS_(cur, kk, tm0));
                float4 fa1 = *(const float4*)(&AS_(cur, kk, tm0 + 32));
                float4 fb0 = *(const float4*)(&BS_(cur, kk, tn0));
                float4 fb1 = *(const float4*)(&BS_(cur, kk, tn0 + 16));
                float am[8] = {fa0.x, fa0.y, fa0.z, fa0.w, fa1.x, fa1.y, fa1.z, fa1.w};
                float bn[8] = {fb0.x, fb0.y, fb0.z, fb0.w, fb1.x, fb1.y, fb1.z, fb1.w};
                #pragma unroll
                for (int i = 0; i < 8; i++)
                    #pragma unroll
                    for (int j = 0; j < 8; j++) acc[i][j] = fmaf(am[i], bn[j], acc[i][j]);
            }
        }
        // store A(t) into nxt (nxt last read at iter t-1, before this iter's barrier)
        #pragma unroll
        for (int j = 0; j < 4; j++) {
            AS_(nxt, aCol + j * 8 + 0, aRow) = ar[j].x;
            AS_(nxt, aCol + j * 8 + 1, aRow) = ar[j].y;
            AS_(nxt, aCol + j * 8 + 2, aRow) = ar[j].z;
            AS_(nxt, aCol + j * 8 + 3, aRow) = ar[j].w;
        }
    }
    // ---- tail ----
    {
        const int cur = (nt - 1) & 1;
        asm volatile("cp.async.wait_group 0;" ::: "memory");
        __syncthreads();
        for (int kh = 0; kh < 2; kh++) {
            #pragma unroll
            for (int kq = 0; kq < 16; kq++) {
                const int kk = kh * 16 + kq;
                float4 fa0 = *(const float4*)(&AS_(cur, kk, tm0));
                float4 fa1 = *(const float4*)(&AS_(cur, kk, tm0 + 32));
                float4 fb0 = *(const float4*)(&BS_(cur, kk, tn0));
                float4 fb1 = *(const float4*)(&BS_(cur, kk, tn0 + 16));
                float am[8] = {fa0.x, fa0.y, fa0.z, fa0.w, fa1.x, fa1.y, fa1.z, fa1.w};
                float bn[8] = {fb0.x, fb0.y, fb0.z, fb0.w, fb1.x, fb1.y, fb1.z, fb1.w};
                #pragma unroll
                for (int i = 0; i < 8; i++)
                    #pragma unroll
                    for (int j = 0; j < 8; j++) acc[i][j] = fmaf(am[i], bn[j], acc[i][j]);
            }
        }
    }
    #undef AS_
    #undef BS_

    float4 bia0, bia1;
    if (bias) {
        bia0 = *(const float4*)(bias + colBase + tn0);
        bia1 = *(const float4*)(bias + colBase + tn0 + 16);
    } else {
        bia0 = make_float4(0.f, 0.f, 0.f, 0.f);
        bia1 = bia0;
    }
    #pragma unroll
    for (int i = 0; i < 8; i++) {
        int mrow = (i < 4) ? (tm0 + i) : (tm0 + 32 + i - 4);
        size_t r = (size_t)(rowBase + mrow);
        float* c0 = Cout + r * N + colBase + tn0;
        float* c1 = c0 + 16;
        float4 v0 = make_float4(acc[i][0] + bia0.x, acc[i][1] + bia0.y,
                                acc[i][2] + bia0.z, acc[i][3] + bia0.w);
        float4 v1 = make_float4(acc[i][4] + bia1.x, acc[i][5] + bia1.y,
                                acc[i][6] + bia1.z, acc[i][7] + bia1.w);
        if (MODE == 1) {
            v0.x = gelu_f(v0.x); v0.y = gelu_f(v0.y); v0.z = gelu_f(v0.z); v0.w = gelu_f(v0.w);
            v1.x = gelu_f(v1.x); v1.y = gelu_f(v1.y); v1.z = gelu_f(v1.z); v1.w = gelu_f(v1.w);
        }
        if (MODE == 2) {
            const float* rr = Res + r * N + colBase + tn0;
            float4 r0 = *(const float4*)rr;
            float4 r1 = *(const float4*)(rr + 16);
            v0.x += r0.x; v0.y += r0.y; v0.z += r0.z; v0.w += r0.w;
            v1.x += r1.x; v1.y += r1.y; v1.z += r1.z; v1.w += r1.w;
        }
        *(float4*)c0 = v0;
        *(float4*)c1 = v1;
    }
}

template <int MODE>
__global__ __launch_bounds__(256, 2) void sgemm_kernel(const float* __restrict__ A,
                                                       const float* __restrict__ B,
                                                       const float* __restrict__ bias,
                                                       const float* __restrict__ Res,
                                                       float* __restrict__ Cout,
                                                       int N, int K) {
    sgemm_body<MODE>(A, B, bias, Res, Cout, N, K, K, blockIdx.y * 128, blockIdx.x * 128);
}

__global__ __launch_bounds__(256, 2) void qkv_kernel(const float* __restrict__ A,
                                                     const float* __restrict__ Wq,
                                                     const float* __restrict__ Wk,
                                                     const float* __restrict__ Wv,
                                                     const float* __restrict__ bq,
                                                     const float* __restrict__ bk,
                                                     const float* __restrict__ bv,
                                                     float* __restrict__ oq,
                                                     float* __restrict__ ok,
                                                     float* __restrict__ ov) {
    const int nblk = CC / 128;
    int which = blockIdx.x / nblk;
    int colBlk = blockIdx.x - which * nblk;
    const float* B = (which == 0) ? Wq : (which == 1) ? Wk : Wv;
    const float* bi = (which == 0) ? bq : (which == 1) ? bk : bv;
    float* O = (which == 0) ? oq : (which == 1) ? ok : ov;
    sgemm_body<0>(A, B, bi, nullptr, O, CC, CC, CC, blockIdx.y * 128, colBlk * 128);
}

__global__ __launch_bounds__(256, 2) void sgemm_split_kernel(const float* __restrict__ A,
                                                             const float* __restrict__ B,
                                                             float* __restrict__ P0,
                                                             float* __restrict__ P1,
                                                             float* __restrict__ P2,
                                                             int N, int Kfull, int Ksplit) {
    const int z = blockIdx.z;
    float* P = (z == 0) ? P0 : (z == 1) ? P1 : P2;
    sgemm_body<0>(A + z * Ksplit, B + (size_t)z * Ksplit * N, nullptr, nullptr, P,
                  N, Ksplit, Kfull, blockIdx.y * 128, blockIdx.x * 128);
}

// ---------------- fused attention v5: 64q x 64k, 128 thr, 8q x 4k fragments --
__device__ __forceinline__ int att_swz(int d, int k) {
    return d * 64 + ((((k >> 2) ^ ((d >> 2) & 15)) << 2) | (k & 3));
}

#define ATT_SMEM_BYTES (4 * 64 * 64 * 4 + 64 * 4)
#define ATT_M0 12.0f

__global__ __launch_bounds__(128, 3) void attn_kernel(const int* __restrict__ idx) {
    extern __shared__ float sm[];
    float* Qt   = sm;
    float* Kt   = sm + 4096;
    float* Vs   = sm + 8192;
    float* Ps   = sm + 12288;
    float* kokf = sm + 16384;

    const int tid = threadIdx.x;
    const int tx = tid & 15, ty = tid >> 4;
    const int b = blockIdx.z, h = blockIdx.y;
    const int q0 = blockIdx.x * 64;

    #pragma unroll
    for (int it = 0; it < 8; it++) {
        int lin = tid + it * 128;
        int qi = lin >> 4, d4 = (lin & 15) << 2;
        float4 v = *(const float4*)&g_q[((size_t)(b * TT + q0 + qi)) * CC + h * 64 + d4];
        Qt[att_swz(d4 + 0, qi)] = v.x;
        Qt[att_swz(d4 + 1, qi)] = v.y;
        Qt[att_swz(d4 + 2, qi)] = v.z;
        Qt[att_swz(d4 + 3, qi)] = v.w;
    }

    float l_r[8];
    float acc_o[8][4];
    #pragma unroll
    for (int i = 0; i < 8; i++) {
        l_r[i] = 0.f;
        #pragma unroll
        for (int j = 0; j < 4; j++) acc_o[i][j] = 0.f;
    }
    __syncthreads();

    for (int kt = 0; kt < TT / 64; kt++) {
        const int kbase = kt * 64;
        #pragma unroll
        for (int it = 0; it < 8; it++) {
            int lin = tid + it * 128;
            int ki = lin >> 4, d4 = (lin & 15) << 2;
            size_t go = ((size_t)(b * TT + kbase + ki)) * CC + h * 64 + d4;
            float4 kv = *(const float4*)&g_k[go];
            float4 vv = *(const float4*)&g_v[go];
            Kt[att_swz(d4 + 0, ki)] = kv.x;
            Kt[att_swz(d4 + 1, ki)] = kv.y;
            Kt[att_swz(d4 + 2, ki)] = kv.z;
            Kt[att_swz(d4 + 3, ki)] = kv.w;
            *(float4*)&Vs[ki * 64 + d4] = vv;
        }
        if (tid < 64) kokf[tid] = (idx[b * TT + kbase + tid] != VV - 1) ? 1.f : 0.f;
        __syncthreads();

        float accs[8][4];
        #pragma unroll
        for (int i = 0; i < 8; i++)
            #pragma unroll
            for (int j = 0; j < 4; j++) accs[i][j] = 0.f;
        #pragma unroll 16
        for (int d = 0; d < 64; d++) {
            int g = (d >> 2) & 15;
            float4 q0v = *(const float4*)&Qt[d * 64 + (((2 * ty) ^ g) << 2)];
            float4 q1v = *(const float4*)&Qt[d * 64 + (((2 * ty + 1) ^ g) << 2)];
            float4 kv = *(const float4*)&Kt[d * 64 + ((tx ^ g) << 2)];
            float am[8] = {q0v.x, q0v.y, q0v.z, q0v.w, q1v.x, q1v.y, q1v.z, q1v.w};
            float bn[4] = {kv.x, kv.y, kv.z, kv.w};
            #pragma unroll
            for (int i = 0; i < 8; i++)
                #pragma unroll
                for (int j = 0; j < 4; j++) accs[i][j] = fmaf(am[i], bn[j], accs[i][j]);
        }

        float km[4];
        #pragma unroll
        for (int j = 0; j < 4; j++) km[j] = kokf[tx * 4 + j];

        #pragma unroll
        for (int i = 0; i < 8; i++) {
            float p[4];
            #pragma unroll
            for (int j = 0; j < 4; j++)
                p[j] = __expf(fmaf(accs[i][j], 0.125f, -ATT_M0)) * km[j];
            l_r[i] += (p[0] + p[1]) + (p[2] + p[3]);
            *(float4*)&Ps[(ty * 8 + i) * 64 + tx * 4] = make_float4(p[0], p[1], p[2], p[3]);
        }
        __syncthreads();

        #pragma unroll 8
        for (int k4 = 0; k4 < 16; k4++) {
            float4 vv[4];
            #pragma unroll
            for (int e = 0; e < 4; e++)
                vv[e] = *(const float4*)&Vs[(k4 * 4 + e) * 64 + tx * 4];
            #pragma unroll
            for (int i = 0; i < 8; i++) {
                float4 pv = *(const float4*)&Ps[(ty * 8 + i) * 64 + k4 * 4];
                float pr[4] = {pv.x, pv.y, pv.z, pv.w};
                #pragma unroll
                for (int e = 0; e < 4; e++) {
                    acc_o[i][0] = fmaf(pr[e], vv[e].x, acc_o[i][0]);
                    acc_o[i][1] = fmaf(pr[e], vv[e].y, acc_o[i][1]);
                    acc_o[i][2] = fmaf(pr[e], vv[e].z, acc_o[i][2]);
                    acc_o[i][3] = fmaf(pr[e], vv[e].w, acc_o[i][3]);
                }
            }
        }
        __syncthreads();
    }

    #pragma unroll
    for (int i = 0; i < 8; i++) {
        #pragma unroll
        for (int o = 8; o > 0; o >>= 1)
            l_r[i] += __shfl_xor_sync(0xffffffffu, l_r[i], o, 16);
    }

    #pragma unroll
    for (int i = 0; i < 8; i++) {
        float invl = 1.0f / l_r[i];
        size_t ob = ((size_t)(b * TT + q0 + ty * 8 + i)) * CC + h * 64 + tx * 4;
        *(float4*)&g_y[ob] = make_float4(acc_o[i][0] * invl, acc_o[i][1] * invl,
                                         acc_o[i][2] * invl, acc_o[i][3] * invl);
    }
}

// ---------------- bf16 conversion: Whead transpose ---------------------------
__global__ __launch_bounds__(256) void convert_wh(const float* __restrict__ Wh) {
    __shared__ float tile[32][33];
    int n0 = blockIdx.x * 32, k0 = blockIdx.y * 32;
    int tx = threadIdx.x & 31, ty = threadIdx.x >> 5;  // 32 x 8
    #pragma unroll
    for (int j = 0; j < 32; j += 8)
        tile[ty + j][tx] = Wh[(size_t)(k0 + ty + j) * VV + n0 + tx];
    __syncthreads();
    #pragma unroll
    for (int j = 0; j < 32; j += 8)
        g_whb[(size_t)(n0 + ty + j) * CC + k0 + tx] = __float2bfloat16(tile[tx][ty + j]);
}

// ---------------- head GEMM: bf16 mma.sync m16n8k16 + ldmatrix fragments -----
__device__ __forceinline__ void ldsm_x4(uint32_t& r0, uint32_t& r1, uint32_t& r2,
                                        uint32_t& r3, const void* p) {
    uint32_t a = (uint32_t)__cvta_generic_to_shared(p);
    asm volatile("ldmatrix.sync.aligned.m8n8.x4.shared.b16 {%0,%1,%2,%3}, [%4];"
                 : "=r"(r0), "=r"(r1), "=r"(r2), "=r"(r3) : "r"(a));
}

__global__ __launch_bounds__(256, 2) void head_gemm(const __nv_bfloat16* __restrict__ A,
                                                    const __nv_bfloat16* __restrict__ Bt,
                                                    float* __restrict__ Cout) {
    __shared__ __align__(16) __nv_bfloat16 As[2][128][40];
    __shared__ __align__(16) __nv_bfloat16 Bs[2][128][40];

    const int tid = threadIdx.x;
    const int rowBase = blockIdx.y * 128, colBase = blockIdx.x * 128;
    const int warp = tid >> 5, lane = tid & 31;
    const int wm = warp & 1, wn = warp >> 1;
    const int g = lane >> 2, t4 = lane & 3;

    const int a_row_off = (lane & 7) + ((lane >> 3) & 1) * 8;
    const int a_k_off   = ((lane >> 4) & 1) * 8;
    const int b_row_off = (lane & 7) + ((lane >> 4) & 1) * 8;
    const int b_k_off   = ((lane >> 3) & 1) * 8;

    const int ldRow = tid >> 1, ldSeg = (tid & 1) * 16;
    const __nv_bfloat16* Agr = A + (size_t)(rowBase + ldRow) * CC + ldSeg;
    const __nv_bfloat16* Bgr = Bt + (size_t)(colBase + ldRow) * CC + ldSeg;

    float c[4][4][4];
    #pragma unroll
    for (int i = 0; i < 4; i++)
        #pragma unroll
        for (int j = 0; j < 4; j++)
            #pragma unroll
            for (int e = 0; e < 4; e++) c[i][j][e] = 0.f;

    const int NT = CC / 32;  // 24
    #pragma unroll
    for (int pb = 0; pb < 2; pb++) {
        cp16(&As[pb][ldRow][ldSeg],     Agr + pb * 32);
        cp16(&As[pb][ldRow][ldSeg + 8], Agr + pb * 32 + 8);
        cp16(&Bs[pb][ldRow][ldSeg],     Bgr + pb * 32);
        cp16(&Bs[pb][ldRow][ldSeg + 8], Bgr + pb * 32 + 8);
        asm volatile("cp.async.commit_group;" ::: "memory");
    }

    for (int kb = 0; kb < NT; kb++) {
        if (kb + 1 < NT) asm volatile("cp.async.wait_group 1;" ::: "memory");
        else             asm volatile("cp.async.wait_group 0;" ::: "memory");
        __syncthreads();
        const int buf = kb & 1;
        #pragma unroll
        for (int kk = 0; kk < 2; kk++) {
            const int ko = kk * 16;
            uint32_t af[4][4], bfr[4][2];
            #pragma unroll
            for (int mt = 0; mt < 4; mt++)
                ldsm_x4(af[mt][0], af[mt][1], af[mt][2], af[mt][3],
                        &As[buf][wm * 64 + mt * 16 + a_row_off][ko + a_k_off]);
            #pragma unroll
            for (int ntp = 0; ntp < 2; ntp++)
                ldsm_x4(bfr[2 * ntp][0], bfr[2 * ntp][1],
                        bfr[2 * ntp + 1][0], bfr[2 * ntp + 1][1],
                        &Bs[buf][wn * 32 + ntp * 16 + b_row_off][ko + b_k_off]);
            #pragma unroll
            for (int mt = 0; mt < 4; mt++)
                #pragma unroll
                for (int nt = 0; nt < 4; nt++)
                    asm volatile(
                        "mma.sync.aligned.m16n8k16.row.col.f32.bf16.bf16.f32 "
                        "{%0,%1,%2,%3}, {%4,%5,%6,%7}, {%8,%9}, {%0,%1,%2,%3};"
                        : "+f"(c[mt][nt][0]), "+f"(c[mt][nt][1]),
                          "+f"(c[mt][nt][2]), "+f"(c[mt][nt][3])
                        : "r"(af[mt][0]), "r"(af[mt][1]), "r"(af[mt][2]), "r"(af[mt][3]),
                          "r"(bfr[nt][0]), "r"(bfr[nt][1]));
        }
        __syncthreads();
        if (kb + 2 < NT) {
            cp16(&As[buf][ldRow][ldSeg],     Agr + (kb + 2) * 32);
            cp16(&As[buf][ldRow][ldSeg + 8], Agr + (kb + 2) * 32 + 8);
            cp16(&Bs[buf][ldRow][ldSeg],     Bgr + (kb + 2) * 32);
            cp16(&Bs[buf][ldRow][ldSeg + 8], Bgr + (kb + 2) * 32 + 8);
            asm volatile("cp.async.commit_group;" ::: "memory");
        }
    }

    #pragma unroll
    for (int mt = 0; mt < 4; mt++) {
        int r0 = rowBase + wm * 64 + mt * 16 + g;
        #pragma unroll
        for (int nt = 0; nt < 4; nt++) {
            int cc0 = colBase + wn * 32 + nt * 8 + 2 * t4;
            *(float2*)&Cout[(size_t)r0 * VV + cc0] =
                make_float2(c[mt][nt][0], c[mt][nt][1]);
            *(float2*)&Cout[(size_t)(r0 + 8) * VV + cc0] =
                make_float2(c[mt][nt][2], c[mt][nt][3]);
        }
    }
}

// ---------------- head finish v2: single stats pass (unshifted sumexp) -------
#define HEAD_EPS 0.05f

__global__ __launch_bounds__(256) void head_finish(float* __restrict__ outArg,
                                                   float* __restrict__ outP,
                                                   float* __restrict__ logits,
                                                   const float* __restrict__ hbuf,
                                                   const float* __restrict__ Whead) {
    const int row = blockIdx.x;
    float* x = logits + (size_t)row * VV;
    const int t = threadIdx.x;
    __shared__ float sred[256];
    __shared__ float smx[256];
    __shared__ int cand[64];
    __shared__ int s_nc;
    __shared__ float s_bv;
    __shared__ int s_bi;

    float mx = -1e30f;
    float se = 0.f;
    for (int j = t; j < VV; j += 256) {
        float v = x[j];
        mx = fmaxf(mx, v);
        se += expf(v);
    }
    smx[t] = mx;
    sred[t] = se;
    __syncthreads();
    for (int s = 128; s > 0; s >>= 1) {
        if (t < s) {
            smx[t] = fmaxf(smx[t], smx[t + s]);
            sred[t] += sred[t + s];
        }
        __syncthreads();
    }
    float rmax = smx[0];
    float lz = logf(sred[0]);
    __syncthreads();
    if (t == 0) s_nc = 0;
    __syncthreads();

    for (int j = t; j < VV; j += 256) {
        float v = x[j];
        if (v >= rmax - HEAD_EPS) {
            int p = atomicAdd(&s_nc, 1);
            if (p < 64) cand[p] = j;
        }
        x[j] = v - lz;
    }
    __syncthreads();

    int nc = min(s_nc, 64);
    if (t == 0) { s_bv = -3e38f; s_bi = VV; }
    __syncthreads();
    const float* hr = hbuf + (size_t)row * CC;
    for (int cd = 0; cd < nc; cd++) {
        int j = cand[cd];
        float part = 0.f;
        for (int k = t; k < CC; k += 256) part += hr[k] * Whead[(size_t)k * VV + j];
        sred[t] = part;
        __syncthreads();
        for (int s = 128; s > 0; s >>= 1) {
            if (t < s) sred[t] += sred[t + s];
            __syncthreads();
        }
        if (t == 0) {
            float val = sred[0];
            if (val > s_bv || (val == s_bv && j < s_bi)) { s_bv = val; s_bi = j; }
        }
        __syncthreads();
    }
    if (t == 0) {
        if (outArg) outArg[row] = (float)s_bi;
        if (outP) outP[row] = expf(s_bv - lz);
    }
}

// ---------------- launch -----------------------------------------------------
extern "C" void kernel_launch(void* const* d_in, const int* in_sizes, int n_in,
                              void* d_out, int out_size) {
    const int* idx   = (const int*)d_in[0];
    const float* tok = (const float*)d_in[1];
    const float* pos = (const float*)d_in[2];
    const float* Wq  = (const float*)d_in[3];
    const float* bq  = (const float*)d_in[4];
    const float* Wk  = (const float*)d_in[5];
    const float* bk  = (const float*)d_in[6];
    const float* Wv  = (const float*)d_in[7];
    const float* bv  = (const float*)d_in[8];
    const float* Wo  = (const float*)d_in[9];
    const float* bo  = (const float*)d_in[10];
    const float* ln1g = (const float*)d_in[11];
    const float* ln1b = (const float*)d_in[12];
    const float* ln2g = (const float*)d_in[13];
    const float* ln2b = (const float*)d_in[14];
    const float* W1  = (const float*)d_in[15];
    const float* b1  = (const float*)d_in[16];
    const float* W2  = (const float*)d_in[17];
    const float* b2  = (const float*)d_in[18];
    const float* lnfg = (const float*)d_in[19];
    const float* lnfb = (const float*)d_in[20];
    const float* Wh  = (const float*)d_in[21];

    float* out = (float*)d_out;
    float* outArg = nullptr;
    float* outP = nullptr;
    float* logits = out;
    if (out_size >= MM * VV + 2 * MM) {
        outArg = out;
        outP = out + MM;
        logits = out + 2 * MM;
    }

    float *px, *ph, *pq, *pk, *pv, *py, *pf;
    __nv_bfloat16 *pab, *pwhb;
    cudaGetSymbolAddress((void**)&px, g_x);
    cudaGetSymbolAddress((void**)&ph, g_h);
    cudaGetSymbolAddress((void**)&pq, g_q);
    cudaGetSymbolAddress((void**)&pk, g_k);
    cudaGetSymbolAddress((void**)&pv, g_v);
    cudaGetSymbolAddress((void**)&py, g_y);
    cudaGetSymbolAddress((void**)&pf, g_ff);
    cudaGetSymbolAddress((void**)&pab, g_ab);
    cudaGetSymbolAddress((void**)&pwhb, g_whb);

    static int attr_set = 0;
    if (!attr_set) {
        cudaFuncSetAttribute(attn_kernel, cudaFuncAttributeMaxDynamicSharedMemorySize,
                             ATT_SMEM_BYTES);
        cudaFuncSetAttribute(sgemm_kernel<1>, cudaFuncAttributeMaxDynamicSharedMemorySize,
                             SGEMM_SMEM_BYTES);
        cudaFuncSetAttribute(qkv_kernel, cudaFuncAttributeMaxDynamicSharedMemorySize,
                             SGEMM_SMEM_BYTES);
        cudaFuncSetAttribute(sgemm_split_kernel, cudaFuncAttributeMaxDynamicSharedMemorySize,
                             SGEMM_SMEM_BYTES);
        attr_set = 1;
    }

    dim3 gemmQKV(3 * CC / 128, MM / 128);    // (18, 32) = 576
    dim3 gemmF(FF / 128, MM / 128);          // (24, 32) = 768
    dim3 gemmCs(CC / 128, MM / 128, 3);      // (6, 32, 3) = 576 split-K
    dim3 gemmH(VV / 128, MM / 128);          // (250, 32)
    dim3 attg(TT / 64, HH, BB);              // (16, 12, 4)
    dim3 whT(VV / 32, CC / 32);              // (1000, 24)

    embed_kernel<<<(MM * CC + 255) / 256, 256>>>(idx, tok, pos);
    convert_wh<<<whT, 256>>>(Wh);
    ln_kernel<0><<<MM / 8, 256>>>(px, ln1g, ln1b, ph);  // layer 0 ln1

    for (int l = 0; l < LL; l++) {
        qkv_kernel<<<gemmQKV, 256, SGEMM_SMEM_BYTES>>>(
            ph, Wq + (size_t)l * CC * CC, Wk + (size_t)l * CC * CC,
            Wv + (size_t)l * CC * CC, bq + l * CC, bk + l * CC, bv + l * CC, pq, pk, pv);
        attn_kernel<<<attg, 128, ATT_SMEM_BYTES>>>(idx);
        sgemm_split_kernel<<<gemmCs, 256, SGEMM_SMEM_BYTES>>>(
            py, Wo + (size_t)l * CC * CC, pq, pk, pv, CC, CC, CC / 3);
        reduce3_ln_kernel<0><<<MM / 8, 256>>>(pq, pk, pv, bo + l * CC, px,
                                              ln2g + l * CC, ln2b + l * CC, ph);
        sgemm_kernel<1><<<gemmF, 256, SGEMM_SMEM_BYTES>>>(
            ph, W1 + (size_t)l * CC * FF, b1 + l * FF, nullptr, pf, FF, CC);
        sgemm_split_kernel<<<gemmCs, 256, SGEMM_SMEM_BYTES>>>(
            pf, W2 + (size_t)l * FF * CC, pq, pk, pv, CC, FF, FF / 3);
        if (l + 1 < LL) {
            reduce3_ln_kernel<0><<<MM / 8, 256>>>(pq, pk, pv, b2 + l * CC, px,
                                                  ln1g + (l + 1) * CC, ln1b + (l + 1) * CC, ph);
        } else {
            reduce3_ln_kernel<1><<<MM / 8, 256>>>(pq, pk, pv, b2 + l * CC, px,
                                                  lnfg, lnfb, ph);
        }
    }

    head_gemm<<<gemmH, 256>>>(pab, pwhb, logits);
    head_finish<<<MM, 256>>>(outArg, outP, logits, ph, Wh);
}